// round 1
// baseline (speedup 1.0000x reference)
#include <cuda_runtime.h>
#include <cstdint>

// Problem constants
#define B_      2048
#define N_      64
#define OBS_    8
#define PRED_   12
#define IN_     6
#define E_      512
#define C_      6
#define CN_     7          // C + 1
#define K_      20
#define DSELF_  120        // IN*(OBS+PRED)
#define DNEI_   48         // IN*OBS
#define RTOT_   (B_ * N_)  // 131072
#define EPSF    1e-4f

#define X_ELEMS ((size_t)B_ * K_ * E_)   // 20,971,520

// ---------------- scratch (__device__ globals; no allocation) ----------------
__device__ float g_A[(size_t)RTOT_ * DNEI_];   // transformed neighbor feats, packed by class (~25 MB)
__device__ int   g_perm[RTOT_];                // packed-pos -> original row
__device__ int   g_cnt[CN_];
__device__ int   g_off[CN_];
__device__ int   g_cur[CN_];
__device__ float g_anchor[(size_t)C_ * K_ * E_];  // 245 KB

// ---------------- kernel 0: reset counters ----------------
__global__ void k_init() {
    int t = threadIdx.x;
    if (t < CN_) { g_cnt[t] = 0; }
}

// ---------------- kernel 1: per-class row counts ----------------
__global__ void k_count(const int* __restrict__ nei_labels) {
    __shared__ int sc[CN_];
    if (threadIdx.x < CN_) sc[threadIdx.x] = 0;
    __syncthreads();
    int i = blockIdx.x * blockDim.x + threadIdx.x;
    if (i < RTOT_) atomicAdd(&sc[nei_labels[i]], 1);
    __syncthreads();
    if (threadIdx.x < CN_ && sc[threadIdx.x] > 0)
        atomicAdd(&g_cnt[threadIdx.x], sc[threadIdx.x]);
}

// ---------------- kernel 2: exclusive prefix over 7 classes ----------------
__global__ void k_prefix() {
    if (threadIdx.x == 0 && blockIdx.x == 0) {
        int acc = 0;
        for (int c = 0; c < CN_; c++) {
            g_off[c] = acc;
            g_cur[c] = acc;
            acc += g_cnt[c];
        }
    }
}

// ---------------- kernel 3: signed-reciprocal transform + scatter into class bins --------
__global__ void k_scatter(const float* __restrict__ neis,
                          const int*   __restrict__ nei_labels) {
    int i = blockIdx.x * blockDim.x + threadIdx.x;
    if (i >= RTOT_) return;
    int c = nei_labels[i];
    int pos = atomicAdd(&g_cur[c], 1);
    g_perm[pos] = i;
    const float4* src = (const float4*)(neis + (size_t)i * DNEI_);
    float4*       dst = (float4*)(g_A + (size_t)pos * DNEI_);
#pragma unroll
    for (int j = 0; j < DNEI_ / 4; j++) {
        float4 v = src[j];
        v.x = (v.x >= 0.f) ? 1.f / (v.x + EPSF) : 1.f / (v.x - EPSF);
        v.y = (v.y >= 0.f) ? 1.f / (v.y + EPSF) : 1.f / (v.y - EPSF);
        v.z = (v.z >= 0.f) ? 1.f / (v.z + EPSF) : 1.f / (v.z - EPSF);
        v.w = (v.w >= 0.f) ? 1.f / (v.w + EPSF) : 1.f / (v.w - EPSF);
        dst[j] = v;
    }
}

// ---------------- kernel 4: grouped GEMM  out[row] = A[row] @ W_nei[c] + b_nei[c] --------
// Tiles: 128 rows x 128 cols, K = 48 (single smem stage).
// 256 threads, each computes an 8x8 register tile.
#define MT 128
#define NT 128
#define GEMM_MAX_MTILES ((RTOT_ / MT) + CN_)   // 1024 + 7
#define GEMM_GRID (GEMM_MAX_MTILES * (E_ / NT))

__global__ __launch_bounds__(256, 2)
void k_gemm(const float* __restrict__ W_nei,
            const float* __restrict__ b_nei,
            float*       __restrict__ out_nei) {
    // ---- block -> (class, m-tile, n-tile) mapping from device-side counts ----
    int nt  = blockIdx.x & 3;         // E_/NT = 4
    int mid = blockIdx.x >> 2;
    int c = -1, mt = 0, acc_t = 0;
#pragma unroll
    for (int cc = 0; cc < CN_; cc++) {
        int t = (g_cnt[cc] + MT - 1) >> 7;
        if (c < 0 && mid < acc_t + t) { c = cc; mt = mid - acc_t; }
        acc_t += t;
    }
    if (c < 0) return;

    int cnt = g_cnt[c];
    int off = g_off[c];
    int m0  = mt * MT;

    __shared__ float As[DNEI_][MT];   // 24 KB, A transposed for coalesced compute reads
    __shared__ float Bs[DNEI_][NT];   // 24 KB

    int tid = threadIdx.x;

    // load A tile: 128 rows x 12 float4 = 1536 float4, 6 per thread
#pragma unroll
    for (int it = 0; it < 6; it++) {
        int idx = tid + it * 256;
        int r = idx / 12, q = idx % 12;
        float4 v = make_float4(0.f, 0.f, 0.f, 0.f);
        if (m0 + r < cnt)
            v = *(const float4*)(g_A + (size_t)(off + m0 + r) * DNEI_ + q * 4);
        As[q * 4 + 0][r] = v.x;
        As[q * 4 + 1][r] = v.y;
        As[q * 4 + 2][r] = v.z;
        As[q * 4 + 3][r] = v.w;
    }
    // load B tile: W_nei[c][k][nt*128 + col], 48 x 32 float4 = 1536 float4
    const float* Wc = W_nei + (size_t)c * DNEI_ * E_ + nt * NT;
#pragma unroll
    for (int it = 0; it < 6; it++) {
        int idx = tid + it * 256;
        int k = idx / 32, q = idx % 32;
        float4 v = *(const float4*)(Wc + (size_t)k * E_ + q * 4);
        *(float4*)(&Bs[k][q * 4]) = v;
    }
    __syncthreads();

    int tcol = tid & 15;        // 16 col-threads  -> 8 cols each
    int trow = tid >> 4;        // 16 row-threads  -> 8 rows each

    float acc[8][8];
#pragma unroll
    for (int i = 0; i < 8; i++)
#pragma unroll
        for (int j = 0; j < 8; j++) acc[i][j] = 0.f;

#pragma unroll 4
    for (int k = 0; k < DNEI_; k++) {
        float a[8], b[8];
        *(float4*)(a)     = *(const float4*)(&As[k][trow * 8]);
        *(float4*)(a + 4) = *(const float4*)(&As[k][trow * 8 + 4]);
        *(float4*)(b)     = *(const float4*)(&Bs[k][tcol * 8]);
        *(float4*)(b + 4) = *(const float4*)(&Bs[k][tcol * 8 + 4]);
#pragma unroll
        for (int i = 0; i < 8; i++)
#pragma unroll
            for (int j = 0; j < 8; j++)
                acc[i][j] += a[i] * b[j];
    }

    // epilogue: add bias, scatter rows back via perm
    const float* bias = b_nei + (size_t)c * E_ + nt * NT + tcol * 8;
    float bv[8];
    *(float4*)(bv)     = *(const float4*)(bias);
    *(float4*)(bv + 4) = *(const float4*)(bias + 4);

#pragma unroll
    for (int i = 0; i < 8; i++) {
        int r = m0 + trow * 8 + i;
        if (r < cnt) {
            int rg = g_perm[off + r];
            float* o = out_nei + (size_t)rg * E_ + nt * NT + tcol * 8;
            float4 v0 = make_float4(acc[i][0] + bv[0], acc[i][1] + bv[1],
                                    acc[i][2] + bv[2], acc[i][3] + bv[3]);
            float4 v1 = make_float4(acc[i][4] + bv[4], acc[i][5] + bv[5],
                                    acc[i][6] + bv[6], acc[i][7] + bv[7]);
            *(float4*)(o)     = v0;
            *(float4*)(o + 4) = v1;
        }
    }
}

// ---------------- kernel 5: anchor_part[c,k,:] = it[c,k] @ W_self[c][48:] + b_self[c] ----
__global__ void k_anchor(const float* __restrict__ init_trajs,
                         const float* __restrict__ W_self,
                         const float* __restrict__ b_self) {
    int c  = blockIdx.x / K_;
    int kk = blockIdx.x % K_;
    __shared__ float tr[PRED_ * IN_];   // 72
    if (threadIdx.x < PRED_ * IN_)
        tr[threadIdx.x] = init_trajs[((size_t)c * K_ + kk) * (PRED_ * IN_) + threadIdx.x];
    __syncthreads();

    int col = threadIdx.x * 4;          // 128 threads x 4 cols = 512
    const float* bb = b_self + (size_t)c * E_ + col;
    float4 acc = *(const float4*)bb;
    const float* W = W_self + ((size_t)c * DSELF_ + DNEI_) * E_ + col;
#pragma unroll 8
    for (int j = 0; j < PRED_ * IN_; j++) {
        float  t = tr[j];
        float4 w = *(const float4*)(W + (size_t)j * E_);
        acc.x += t * w.x; acc.y += t * w.y; acc.z += t * w.z; acc.w += t * w.w;
    }
    *(float4*)(g_anchor + ((size_t)c * K_ + kk) * E_ + col) = acc;
}

// ---------------- kernel 6: x[b,k,:] = obs[b] @ W_self[c][:48] + anchor[c,k,:] ----------
__global__ void k_x(const float* __restrict__ obs,
                    const float* __restrict__ W_self,
                    const int*   __restrict__ self_labels,
                    float*       __restrict__ out_x) {
    int b = blockIdx.x;
    __shared__ float ob[DNEI_];
    if (threadIdx.x < DNEI_)
        ob[threadIdx.x] = obs[(size_t)b * DNEI_ + threadIdx.x];
    __syncthreads();

    int c   = self_labels[b];
    int col = threadIdx.x * 4;          // 128 threads x 4 cols
    const float* W = W_self + (size_t)c * DSELF_ * E_ + col;
    float4 acc = make_float4(0.f, 0.f, 0.f, 0.f);
#pragma unroll 8
    for (int j = 0; j < DNEI_; j++) {
        float  t = ob[j];
        float4 w = *(const float4*)(W + (size_t)j * E_);
        acc.x += t * w.x; acc.y += t * w.y; acc.z += t * w.z; acc.w += t * w.w;
    }
#pragma unroll
    for (int kk = 0; kk < K_; kk++) {
        float4 an = *(const float4*)(g_anchor + ((size_t)c * K_ + kk) * E_ + col);
        float4 v  = make_float4(acc.x + an.x, acc.y + an.y, acc.z + an.z, acc.w + an.w);
        *(float4*)(out_x + ((size_t)b * K_ + kk) * E_ + col) = v;
    }
}

// ---------------- launcher ----------------
extern "C" void kernel_launch(void* const* d_in, const int* in_sizes, int n_in,
                              void* d_out, int out_size) {
    const float* obs         = (const float*)d_in[0];
    const float* neis        = (const float*)d_in[1];
    const float* init_trajs  = (const float*)d_in[2];
    const float* W_self      = (const float*)d_in[3];
    const float* b_self      = (const float*)d_in[4];
    const float* W_nei       = (const float*)d_in[5];
    const float* b_nei       = (const float*)d_in[6];
    const int*   self_labels = (const int*)d_in[7];
    const int*   nei_labels  = (const int*)d_in[8];

    float* out_x   = (float*)d_out;
    float* out_nei = (float*)d_out + X_ELEMS;

    // nei_feats path
    k_init<<<1, 32>>>();
    k_count<<<(RTOT_ + 255) / 256, 256>>>(nei_labels);
    k_prefix<<<1, 32>>>();
    k_scatter<<<(RTOT_ + 255) / 256, 256>>>(neis, nei_labels);
    k_gemm<<<GEMM_GRID, 256>>>(W_nei, b_nei, out_nei);

    // x path
    k_anchor<<<C_ * K_, 128>>>(init_trajs, W_self, b_self);
    k_x<<<B_, 128>>>(obs, W_self, self_labels, out_x);
}